// round 1
// baseline (speedup 1.0000x reference)
#include <cuda_runtime.h>
#include <math.h>

#define T_SEQ 2048
#define DIM_   1024
#define NH     8
#define HD     128
#define ATTN_SCALE 0.12f
#define RMS_EPS 1.1920929e-7f

// -------------------- scratch (static device globals; no allocs) --------------------
__device__ float g_qkv[(size_t)T_SEQ * 3 * DIM_];   // 24 MB : [t][3072]
__device__ float g_q  [(size_t)NH * T_SEQ * HD];    // 8 MB  : [h][t][c]
__device__ float g_k  [(size_t)NH * T_SEQ * HD];
__device__ float g_v  [(size_t)NH * T_SEQ * HD];
__device__ float g_y  [(size_t)T_SEQ * DIM_];       // 8 MB  : [t][h*128+c]

// -------------------- GEMM: C[M,N] = A[M,K] @ B[N,K]^T  (all row-major) -------------
// 128x128 block tile, BK=16, 256 threads, 8x8 micro-tile per thread.
__global__ __launch_bounds__(256, 2)
void gemm_nt(const float* __restrict__ A, const float* __restrict__ B,
             float* __restrict__ C, int M, int N, int K)
{
    __shared__ float As[16][128];
    __shared__ float Bs[16][128];

    const int tid = threadIdx.x;
    const int tx  = tid & 15;
    const int ty  = tid >> 4;
    const int m0  = blockIdx.y * 128;
    const int n0  = blockIdx.x * 128;

    float acc[8][8];
#pragma unroll
    for (int i = 0; i < 8; i++)
#pragma unroll
        for (int j = 0; j < 8; j++) acc[i][j] = 0.0f;

    for (int k0 = 0; k0 < K; k0 += 16) {
#pragma unroll
        for (int p = 0; p < 2; p++) {
            int f   = tid + p * 256;          // 0..511
            int row = f >> 2;                 // 0..127
            int kq  = (f & 3) << 2;           // 0,4,8,12
            float4 va = *(const float4*)(A + (size_t)(m0 + row) * K + k0 + kq);
            As[kq + 0][row] = va.x; As[kq + 1][row] = va.y;
            As[kq + 2][row] = va.z; As[kq + 3][row] = va.w;
            float4 vb = *(const float4*)(B + (size_t)(n0 + row) * K + k0 + kq);
            Bs[kq + 0][row] = vb.x; Bs[kq + 1][row] = vb.y;
            Bs[kq + 2][row] = vb.z; Bs[kq + 3][row] = vb.w;
        }
        __syncthreads();

#pragma unroll
        for (int kk = 0; kk < 16; kk++) {
            float a[8], b[8];
            *(float4*)(a)     = *(const float4*)&As[kk][ty * 8];
            *(float4*)(a + 4) = *(const float4*)&As[kk][ty * 8 + 4];
            *(float4*)(b)     = *(const float4*)&Bs[kk][tx * 8];
            *(float4*)(b + 4) = *(const float4*)&Bs[kk][tx * 8 + 4];
#pragma unroll
            for (int i = 0; i < 8; i++)
#pragma unroll
                for (int j = 0; j < 8; j++)
                    acc[i][j] = fmaf(a[i], b[j], acc[i][j]);
        }
        __syncthreads();
    }

#pragma unroll
    for (int i = 0; i < 8; i++) {
        float4 c0 = make_float4(acc[i][0], acc[i][1], acc[i][2], acc[i][3]);
        float4 c1 = make_float4(acc[i][4], acc[i][5], acc[i][6], acc[i][7]);
        float* crow = C + (size_t)(m0 + ty * 8 + i) * N + n0 + tx * 8;
        *(float4*)(crow)     = c0;
        *(float4*)(crow + 4) = c1;
    }
}

// -------------------- transform: rmsnorm + rotary (q,k), lambda mix (v) -------------
// grid (T, NH), 128 threads; thread c handles channel c of head h at token t.
__global__ __launch_bounds__(128)
void transform_kernel(const float* __restrict__ ve,
                      const float* __restrict__ lambdas)
{
    const int t = blockIdx.x;
    const int h = blockIdx.y;
    const int c = threadIdx.x;
    const int lane = c & 31;
    const int wid  = c >> 5;

    const float* base = g_qkv + (size_t)t * (3 * DIM_);
    float qv = base[            h * HD + c];
    float kv = base[DIM_      + h * HD + c];
    float vv = base[2 * DIM_  + h * HD + c];

    // sum of squares over 128 channels (q and k)
    float sq = qv * qv;
    float sk = kv * kv;
#pragma unroll
    for (int off = 16; off >= 1; off >>= 1) {
        sq += __shfl_xor_sync(0xffffffffu, sq, off);
        sk += __shfl_xor_sync(0xffffffffu, sk, off);
    }
    __shared__ float wq[4], wk[4];
    __shared__ float rq, rk;
    __shared__ float qn[128], kn[128];
    if (lane == 0) { wq[wid] = sq; wk[wid] = sk; }
    __syncthreads();
    if (c == 0) {
        float s1 = wq[0] + wq[1] + wq[2] + wq[3];
        float s2 = wk[0] + wk[1] + wk[2] + wk[3];
        rq = rsqrtf(s1 * (1.0f / 128.0f) + RMS_EPS);
        rk = rsqrtf(s2 * (1.0f / 128.0f) + RMS_EPS);
    }
    __syncthreads();
    qn[c] = qv * rq;
    kn[c] = kv * rk;
    __syncthreads();

    // rotary: x1 = [0,64), x2 = [64,128); ang = concat(freq(32), zeros(32))
    int j = c & 63;
    float cosv, sinv;
    if (j < 32) {
        float tj = (float)j / 31.0f;                       // matches f32 linspace
        float fr = (float)exp2(-10.0 * (double)tj);        // (1/1024)^tj, f32-rounded
        float th = (float)t * fr;                          // f32 theta (matches ref)
        cosv = (float)cos((double)th);                     // accurate trig on same theta
        sinv = (float)sin((double)th);
    } else {
        cosv = 1.0f; sinv = 0.0f;
    }

    float qo, ko;
    if (c < 64) {
        qo =  qn[c] * cosv + qn[c + 64] * sinv;
        ko =  kn[c] * cosv + kn[c + 64] * sinv;
    } else {
        qo = -qn[c - 64] * sinv + qn[c] * cosv;
        ko = -kn[c - 64] * sinv + kn[c] * cosv;
    }

    size_t oidx = ((size_t)h * T_SEQ + t) * HD + c;
    g_q[oidx] = qo;
    g_k[oidx] = ko;

    float vev = ve[(size_t)t * DIM_ + h * HD + c];
    g_v[oidx] = lambdas[0] * vv + lambdas[1] * vev;
}

// -------------------- flash attention (causal, online softmax) ----------------------
// grid (T/64, NH), 256 threads (16x16). BM=BN=64. Q/K stored k-major in SMEM.
// Thread (ty,tx): S micro-tile rows ty*4..+3, cols tx*4..+3;
//                 O ownership rows ty*4..+3, cols tx*8..+7.
#define ATT_SMEM_FLOATS (128*64 + 128*64 + 64*128 + 64*64)  // Qs,Ks,Vs,Ps = 28672
__global__ __launch_bounds__(256)
void attn_kernel()
{
    extern __shared__ float sm[];
    float* Qs = sm;                 // [128][64]  k-major
    float* Ks = sm + 128 * 64;      // [128][64]  k-major
    float* Vs = sm + 2 * 128 * 64;  // [64][128]  row-major
    float* Ps = sm + 3 * 128 * 64;  // [64][64]

    const int tid = threadIdx.x;
    const int tx  = tid & 15;
    const int ty  = tid >> 4;
    const int h   = blockIdx.y;
    const int q0  = blockIdx.x * 64;

    const float* qh = g_q + (size_t)h * T_SEQ * HD;
    const float* kh = g_k + (size_t)h * T_SEQ * HD;
    const float* vh = g_v + (size_t)h * T_SEQ * HD;

    // load Q tile transposed: Qs[c][r]
#pragma unroll
    for (int p = 0; p < 8; p++) {
        int f   = tid + p * 256;      // 0..2047
        int row = f >> 5;             // 0..63
        int c   = (f & 31) << 2;      // 0..124
        float4 v = *(const float4*)&qh[(size_t)(q0 + row) * HD + c];
        Qs[(c + 0) * 64 + row] = v.x; Qs[(c + 1) * 64 + row] = v.y;
        Qs[(c + 2) * 64 + row] = v.z; Qs[(c + 3) * 64 + row] = v.w;
    }

    float m_i[4], l_i[4], O[4][8];
#pragma unroll
    for (int i = 0; i < 4; i++) {
        m_i[i] = -INFINITY; l_i[i] = 0.0f;
#pragma unroll
        for (int j = 0; j < 8; j++) O[i][j] = 0.0f;
    }

    const int ntiles = blockIdx.x + 1;
    for (int t = 0; t < ntiles; t++) {
        const int s0 = t * 64;
        __syncthreads();   // prior iteration done with Ks/Vs (also orders Qs load)

        // load K transposed, V row-major
#pragma unroll
        for (int p = 0; p < 8; p++) {
            int f   = tid + p * 256;
            int row = f >> 5;
            int c   = (f & 31) << 2;
            float4 vk = *(const float4*)&kh[(size_t)(s0 + row) * HD + c];
            Ks[(c + 0) * 64 + row] = vk.x; Ks[(c + 1) * 64 + row] = vk.y;
            Ks[(c + 2) * 64 + row] = vk.z; Ks[(c + 3) * 64 + row] = vk.w;
            float4 vv = *(const float4*)&vh[(size_t)(s0 + row) * HD + c];
            *(float4*)&Vs[row * 128 + c] = vv;
        }
        __syncthreads();

        // S = Q K^T  (4x4 micro-tile)
        float acc[4][4];
#pragma unroll
        for (int i = 0; i < 4; i++)
#pragma unroll
            for (int j = 0; j < 4; j++) acc[i][j] = 0.0f;

#pragma unroll 8
        for (int kk = 0; kk < 128; kk++) {
            float4 a = *(const float4*)&Qs[kk * 64 + ty * 4];
            float4 b = *(const float4*)&Ks[kk * 64 + tx * 4];
            float av[4] = {a.x, a.y, a.z, a.w};
            float bv[4] = {b.x, b.y, b.z, b.w};
#pragma unroll
            for (int i = 0; i < 4; i++)
#pragma unroll
                for (int j = 0; j < 4; j++)
                    acc[i][j] = fmaf(av[i], bv[j], acc[i][j]);
        }

        // scale + causal mask (only the diagonal tile needs masking)
        const bool diag = (t == ntiles - 1) && (s0 == q0);
#pragma unroll
        for (int i = 0; i < 4; i++)
#pragma unroll
            for (int j = 0; j < 4; j++) {
                float s = acc[i][j] * ATTN_SCALE;
                if (diag && (s0 + tx * 4 + j) > (q0 + ty * 4 + i)) s = -INFINITY;
                acc[i][j] = s;
            }

        // online softmax: per-row reduce across 16 tx lanes (within warp)
        float alpha[4];
#pragma unroll
        for (int i = 0; i < 4; i++) {
            float tmax = fmaxf(fmaxf(acc[i][0], acc[i][1]), fmaxf(acc[i][2], acc[i][3]));
#pragma unroll
            for (int off = 8; off >= 1; off >>= 1)
                tmax = fmaxf(tmax, __shfl_xor_sync(0xffffffffu, tmax, off));
            float mn = fmaxf(m_i[i], tmax);
            float al = __expf(m_i[i] - mn);     // exp(-inf)=0 on first tile
            float rs = 0.0f;
#pragma unroll
            for (int j = 0; j < 4; j++) {
                float p = __expf(acc[i][j] - mn);   // masked -> exp(-inf)=0
                acc[i][j] = p;
                rs += p;
            }
#pragma unroll
            for (int off = 8; off >= 1; off >>= 1)
                rs += __shfl_xor_sync(0xffffffffu, rs, off);
            l_i[i] = l_i[i] * al + rs;
            m_i[i] = mn;
            alpha[i] = al;
        }

        // publish P, rescale O
#pragma unroll
        for (int i = 0; i < 4; i++) {
#pragma unroll
            for (int j = 0; j < 4; j++)
                Ps[(ty * 4 + i) * 64 + tx * 4 + j] = acc[i][j];
#pragma unroll
            for (int j = 0; j < 8; j++) O[i][j] *= alpha[i];
        }
        __syncthreads();

        // O += P @ V   (rows ty*4..+3, cols tx*8..+7)
#pragma unroll 4
        for (int j = 0; j < 64; j++) {
            float4 v0 = *(const float4*)&Vs[j * 128 + tx * 8];
            float4 v1 = *(const float4*)&Vs[j * 128 + tx * 8 + 4];
#pragma unroll
            for (int i = 0; i < 4; i++) {
                float p = Ps[(ty * 4 + i) * 64 + j];
                O[i][0] = fmaf(p, v0.x, O[i][0]);
                O[i][1] = fmaf(p, v0.y, O[i][1]);
                O[i][2] = fmaf(p, v0.z, O[i][2]);
                O[i][3] = fmaf(p, v0.w, O[i][3]);
                O[i][4] = fmaf(p, v1.x, O[i][4]);
                O[i][5] = fmaf(p, v1.y, O[i][5]);
                O[i][6] = fmaf(p, v1.z, O[i][6]);
                O[i][7] = fmaf(p, v1.w, O[i][7]);
            }
        }
    }

    // epilogue: O/l -> g_y[t][h*128 + c]
#pragma unroll
    for (int i = 0; i < 4; i++) {
        float inv = 1.0f / l_i[i];
        float* yrow = g_y + (size_t)(q0 + ty * 4 + i) * DIM_ + h * HD + tx * 8;
        float4 o0 = make_float4(O[i][0] * inv, O[i][1] * inv, O[i][2] * inv, O[i][3] * inv);
        float4 o1 = make_float4(O[i][4] * inv, O[i][5] * inv, O[i][6] * inv, O[i][7] * inv);
        *(float4*)(yrow)     = o0;
        *(float4*)(yrow + 4) = o1;
    }
}

// -------------------- launch ---------------------------------------------------------
extern "C" void kernel_launch(void* const* d_in, const int* in_sizes, int n_in,
                              void* d_out, int out_size)
{
    const float* x        = (const float*)d_in[0];
    const float* ve       = (const float*)d_in[1];
    const float* qkv_w    = (const float*)d_in[2];   // (3*1024, 1024) row-major
    const float* lambdas  = (const float*)d_in[3];
    const float* c_proj_w = (const float*)d_in[4];   // (1024, 1024) row-major
    float* out = (float*)d_out;

    float *p_qkv, *p_y;
    cudaGetSymbolAddress((void**)&p_qkv, g_qkv);
    cudaGetSymbolAddress((void**)&p_y,   g_y);

    // 1) QKV projection: g_qkv[2048,3072] = x[2048,1024] @ qkv_w^T
    gemm_nt<<<dim3(3 * DIM_ / 128, T_SEQ / 128), 256>>>(x, qkv_w, p_qkv, T_SEQ, 3 * DIM_, DIM_);

    // 2) rmsnorm + rotary + v mix
    transform_kernel<<<dim3(T_SEQ, NH), 128>>>(ve, lambdas);

    // 3) causal flash attention
    static int attn_cfg_done = 0;
    (void)attn_cfg_done;
    cudaFuncSetAttribute(attn_kernel, cudaFuncAttributeMaxDynamicSharedMemorySize,
                         ATT_SMEM_FLOATS * (int)sizeof(float));
    attn_kernel<<<dim3(T_SEQ / 64, NH), 256, ATT_SMEM_FLOATS * sizeof(float)>>>();

    // 4) output projection: out[2048,1024] = g_y @ c_proj_w^T
    gemm_nt<<<dim3(DIM_ / 128, T_SEQ / 128), 256>>>(p_y, c_proj_w, out, T_SEQ, DIM_, DIM_);
}

// round 2
// speedup vs baseline: 2.9463x; 2.9463x over previous
#include <cuda_runtime.h>
#include <math.h>

#define T_SEQ 2048
#define DIM_   1024
#define NH     8
#define HD     128
#define ATTN_SCALE 0.12f
#define RMS_EPS 1.1920929e-7f
#define LOG2E 1.4426950408889634f

// -------------------- scratch (static device globals; no allocs) --------------------
__device__ float g_qkv[(size_t)T_SEQ * 3 * DIM_];   // [t][3072]
__device__ float g_q  [(size_t)NH * T_SEQ * HD];    // [h][t][c]  (tf32-rounded)
__device__ float g_k  [(size_t)NH * T_SEQ * HD];
__device__ float g_v  [(size_t)NH * T_SEQ * HD];
__device__ float g_y  [(size_t)T_SEQ * DIM_];       // [t][h*128+c]

// -------------------- tf32 helpers ---------------------------------------------------
__device__ __forceinline__ unsigned f2tf(float f) {
    unsigned u;
    asm("cvt.rna.tf32.f32 %0, %1;" : "=r"(u) : "f"(f));
    return u;
}

__device__ __forceinline__ void mma_tf32(float c[4], const unsigned a[4], const unsigned b[2]) {
    asm volatile(
        "mma.sync.aligned.m16n8k8.row.col.f32.tf32.tf32.f32 "
        "{%0,%1,%2,%3}, {%4,%5,%6,%7}, {%8,%9}, {%0,%1,%2,%3};"
        : "+f"(c[0]), "+f"(c[1]), "+f"(c[2]), "+f"(c[3])
        : "r"(a[0]), "r"(a[1]), "r"(a[2]), "r"(a[3]), "r"(b[0]), "r"(b[1]));
}

// -------------------- GEMM (tensor core): C[M,N] = A[M,K] @ B[N,K]^T -----------------
// 128x128 block tile, BK=32, 256 threads (8 warps, 2m x 4n), warp tile 64x32.
// SMEM row stride 40 floats: fragment LDS banks = (8*row + k) % 32 -> conflict-free.
__global__ __launch_bounds__(256)
void gemm_nt_tc(const float* __restrict__ A, const float* __restrict__ B,
                float* __restrict__ C, int M, int N, int K)
{
    __shared__ unsigned As[128 * 40];
    __shared__ unsigned Bs[128 * 40];

    const int tid  = threadIdx.x;
    const int lane = tid & 31;
    const int wid  = tid >> 5;
    const int wm   = wid >> 2;   // 0..1 : 64 rows
    const int wn   = wid & 3;    // 0..3 : 32 cols
    const int m0   = blockIdx.y * 128;
    const int n0   = blockIdx.x * 128;

    float acc[4][4][4];
#pragma unroll
    for (int i = 0; i < 4; i++)
#pragma unroll
        for (int j = 0; j < 4; j++)
#pragma unroll
            for (int r = 0; r < 4; r++) acc[i][j][r] = 0.0f;

    for (int k0 = 0; k0 < K; k0 += 32) {
#pragma unroll
        for (int p = 0; p < 4; p++) {
            int f   = tid + p * 256;       // 0..1023
            int row = f >> 3;              // 0..127
            int kq  = (f & 7) << 2;        // 0..28
            float4 va = *(const float4*)(A + (size_t)(m0 + row) * K + k0 + kq);
            uint4 ua = make_uint4(f2tf(va.x), f2tf(va.y), f2tf(va.z), f2tf(va.w));
            *(uint4*)&As[row * 40 + kq] = ua;
            float4 vb = *(const float4*)(B + (size_t)(n0 + row) * K + k0 + kq);
            uint4 ub = make_uint4(f2tf(vb.x), f2tf(vb.y), f2tf(vb.z), f2tf(vb.w));
            *(uint4*)&Bs[row * 40 + kq] = ub;
        }
        __syncthreads();

#pragma unroll
        for (int ks = 0; ks < 4; ks++) {
            const int kk = ks * 8 + (lane & 3);
            unsigned a[4][4];
#pragma unroll
            for (int i = 0; i < 4; i++) {
                int r = wm * 64 + i * 16 + (lane >> 2);
                a[i][0] = As[r * 40 + kk];
                a[i][1] = As[(r + 8) * 40 + kk];
                a[i][2] = As[r * 40 + kk + 4];
                a[i][3] = As[(r + 8) * 40 + kk + 4];
            }
#pragma unroll
            for (int j = 0; j < 4; j++) {
                int n = wn * 32 + j * 8 + (lane >> 2);
                unsigned b[2];
                b[0] = Bs[n * 40 + kk];
                b[1] = Bs[n * 40 + kk + 4];
#pragma unroll
                for (int i = 0; i < 4; i++) mma_tf32(acc[i][j], a[i], b);
            }
        }
        __syncthreads();
    }

#pragma unroll
    for (int i = 0; i < 4; i++) {
        int row0 = m0 + wm * 64 + i * 16 + (lane >> 2);
#pragma unroll
        for (int j = 0; j < 4; j++) {
            int col = n0 + wn * 32 + j * 8 + 2 * (lane & 3);
            *(float2*)&C[(size_t)row0 * N + col]       = make_float2(acc[i][j][0], acc[i][j][1]);
            *(float2*)&C[(size_t)(row0 + 8) * N + col] = make_float2(acc[i][j][2], acc[i][j][3]);
        }
    }
}

// -------------------- transform: rmsnorm + rotary (q,k), lambda mix (v) -------------
__global__ __launch_bounds__(128)
void transform_kernel(const float* __restrict__ ve,
                      const float* __restrict__ lambdas)
{
    const int t = blockIdx.x;
    const int h = blockIdx.y;
    const int c = threadIdx.x;
    const int lane = c & 31;
    const int wid  = c >> 5;

    const float* base = g_qkv + (size_t)t * (3 * DIM_);
    float qv = base[            h * HD + c];
    float kv = base[DIM_      + h * HD + c];
    float vv = base[2 * DIM_  + h * HD + c];

    float sq = qv * qv;
    float sk = kv * kv;
#pragma unroll
    for (int off = 16; off >= 1; off >>= 1) {
        sq += __shfl_xor_sync(0xffffffffu, sq, off);
        sk += __shfl_xor_sync(0xffffffffu, sk, off);
    }
    __shared__ float wq[4], wk[4];
    __shared__ float rq, rk;
    __shared__ float qn[128], kn[128];
    if (lane == 0) { wq[wid] = sq; wk[wid] = sk; }
    __syncthreads();
    if (c == 0) {
        float s1 = wq[0] + wq[1] + wq[2] + wq[3];
        float s2 = wk[0] + wk[1] + wk[2] + wk[3];
        rq = rsqrtf(s1 * (1.0f / 128.0f) + RMS_EPS);
        rk = rsqrtf(s2 * (1.0f / 128.0f) + RMS_EPS);
    }
    __syncthreads();
    qn[c] = qv * rq;
    kn[c] = kv * rk;
    __syncthreads();

    int j = c & 63;
    float cosv, sinv;
    if (j < 32) {
        float tj = (float)j / 31.0f;
        float fr = (float)exp2(-10.0 * (double)tj);
        float th = (float)t * fr;
        cosv = (float)cos((double)th);
        sinv = (float)sin((double)th);
    } else {
        cosv = 1.0f; sinv = 0.0f;
    }

    float qo, ko;
    if (c < 64) {
        qo =  qn[c] * cosv + qn[c + 64] * sinv;
        ko =  kn[c] * cosv + kn[c + 64] * sinv;
    } else {
        qo = -qn[c - 64] * sinv + qn[c] * cosv;
        ko = -kn[c - 64] * sinv + kn[c] * cosv;
    }

    size_t oidx = ((size_t)h * T_SEQ + t) * HD + c;
    // store tf32-rounded values so attention tiles need no conversion
    g_q[oidx] = __uint_as_float(f2tf(qo));
    g_k[oidx] = __uint_as_float(f2tf(ko));

    float vev = ve[(size_t)t * DIM_ + h * HD + c];
    g_v[oidx] = __uint_as_float(f2tf(lambdas[0] * vv + lambdas[1] * vev));
}

// -------------------- flash attention (tensor core, causal) -------------------------
// BM=64 q-rows per block, BN=64 s per tile. 256 threads = 8 warps:
//   wm = wid>>1 (16 rows each), wn = wid&1 (S: 32 cols / O: 64 cols each).
// SMEM strides chosen for conflict-free fragment LDS:
//   Q,K: 132 (%32==4 -> 4r+k), V: 136 (%32==8 -> 8s+d), P: 68 (%32==4).
#define QS_OFF 0
#define KS_OFF (64 * 132)
#define VS_OFF (KS_OFF + 64 * 132)
#define PS_OFF (VS_OFF + 64 * 136)
#define MR_OFF (PS_OFF + 64 * 68)     // mred: 2*64 floats
#define SR_OFF (MR_OFF + 128)         // sred: 2*64 floats
#define ATT_SMEM_WORDS (SR_OFF + 128)

__global__ __launch_bounds__(256)
void attn_tc()
{
    extern __shared__ unsigned sm[];
    unsigned* Qs = sm + QS_OFF;
    unsigned* Ks = sm + KS_OFF;
    unsigned* Vs = sm + VS_OFF;
    unsigned* Ps = sm + PS_OFF;
    float* mred = (float*)(sm + MR_OFF);
    float* sred = (float*)(sm + SR_OFF);

    const int tid  = threadIdx.x;
    const int lane = tid & 31;
    const int wid  = tid >> 5;
    const int wm   = wid >> 1;   // 0..3
    const int wn   = wid & 1;    // 0..1

    const int bid = blockIdx.x;
    const int h   = bid & 7;
    const int qt  = (T_SEQ / 64 - 1) - (bid >> 3);  // heavy tiles scheduled first
    const int q0  = qt * 64;

    const unsigned* qh = (const unsigned*)g_q + (size_t)h * T_SEQ * HD;
    const unsigned* kh = (const unsigned*)g_k + (size_t)h * T_SEQ * HD;
    const unsigned* vh = (const unsigned*)g_v + (size_t)h * T_SEQ * HD;

    // load Q tile [64][128] (row stride 132)
#pragma unroll
    for (int p = 0; p < 8; p++) {
        int f   = tid + p * 256;
        int row = f >> 5;
        int c   = (f & 31) << 2;
        uint4 v = *(const uint4*)&qh[(size_t)(q0 + row) * HD + c];
        *(uint4*)&Qs[row * 132 + c] = v;
    }

    const int lr0 = wm * 16 + (lane >> 2);   // local row
    const int lr1 = lr0 + 8;

    float m_i[2] = {-INFINITY, -INFINITY};
    float l_i[2] = {0.0f, 0.0f};
    float O[8][4];
#pragma unroll
    for (int nf = 0; nf < 8; nf++)
#pragma unroll
        for (int r = 0; r < 4; r++) O[nf][r] = 0.0f;

    for (int t = 0; t <= qt; t++) {
        const int s0 = t * 64;
        __syncthreads();   // previous PV done with Ks/Vs (and Qs load on t=0)

#pragma unroll
        for (int p = 0; p < 8; p++) {
            int f   = tid + p * 256;
            int row = f >> 5;
            int c   = (f & 31) << 2;
            uint4 vk = *(const uint4*)&kh[(size_t)(s0 + row) * HD + c];
            *(uint4*)&Ks[row * 132 + c] = vk;
            uint4 vv = *(const uint4*)&vh[(size_t)(s0 + row) * HD + c];
            *(uint4*)&Vs[row * 136 + c] = vv;
        }
        __syncthreads();

        // ---- S = Q K^T (warp: rows wm*16..+16, cols wn*32..+32) ----
        float sacc[4][4];
#pragma unroll
        for (int j = 0; j < 4; j++)
#pragma unroll
            for (int r = 0; r < 4; r++) sacc[j][r] = 0.0f;

#pragma unroll
        for (int ks = 0; ks < 16; ks++) {
            const int kk = ks * 8 + (lane & 3);
            unsigned a[4];
            a[0] = Qs[lr0 * 132 + kk];
            a[1] = Qs[lr1 * 132 + kk];
            a[2] = Qs[lr0 * 132 + kk + 4];
            a[3] = Qs[lr1 * 132 + kk + 4];
#pragma unroll
            for (int j = 0; j < 4; j++) {
                int n = wn * 32 + j * 8 + (lane >> 2);
                unsigned b[2];
                b[0] = Ks[n * 132 + kk];
                b[1] = Ks[n * 132 + kk + 4];
                mma_tf32(sacc[j], a, b);
            }
        }

        // scale + causal mask
        const bool diag = (s0 == q0);
        const int gr0 = q0 + lr0, gr1 = q0 + lr1;
#pragma unroll
        for (int j = 0; j < 4; j++) {
            int c0 = s0 + wn * 32 + j * 8 + 2 * (lane & 3);
            float v0 = sacc[j][0] * ATTN_SCALE;
            float v1 = sacc[j][1] * ATTN_SCALE;
            float v2 = sacc[j][2] * ATTN_SCALE;
            float v3 = sacc[j][3] * ATTN_SCALE;
            if (diag) {
                if (c0     > gr0) v0 = -INFINITY;
                if (c0 + 1 > gr0) v1 = -INFINITY;
                if (c0     > gr1) v2 = -INFINITY;
                if (c0 + 1 > gr1) v3 = -INFINITY;
            }
            sacc[j][0] = v0; sacc[j][1] = v1; sacc[j][2] = v2; sacc[j][3] = v3;
        }

        // ---- row max (quad reduce, then cross-warp via SMEM) ----
        float mx0 = fmaxf(fmaxf(sacc[0][0], sacc[0][1]), fmaxf(sacc[1][0], sacc[1][1]));
        mx0 = fmaxf(mx0, fmaxf(fmaxf(sacc[2][0], sacc[2][1]), fmaxf(sacc[3][0], sacc[3][1])));
        float mx1 = fmaxf(fmaxf(sacc[0][2], sacc[0][3]), fmaxf(sacc[1][2], sacc[1][3]));
        mx1 = fmaxf(mx1, fmaxf(fmaxf(sacc[2][2], sacc[2][3]), fmaxf(sacc[3][2], sacc[3][3])));
#pragma unroll
        for (int off = 1; off <= 2; off <<= 1) {
            mx0 = fmaxf(mx0, __shfl_xor_sync(0xffffffffu, mx0, off));
            mx1 = fmaxf(mx1, __shfl_xor_sync(0xffffffffu, mx1, off));
        }
        if ((lane & 3) == 0) {
            mred[wn * 64 + lr0] = mx0;
            mred[wn * 64 + lr1] = mx1;
        }
        __syncthreads();
        float mn0 = fmaxf(m_i[0], fmaxf(mred[lr0], mred[64 + lr0]));
        float mn1 = fmaxf(m_i[1], fmaxf(mred[lr1], mred[64 + lr1]));

        // ---- exp + P store + row sum ----
        float rs0 = 0.0f, rs1 = 0.0f;
#pragma unroll
        for (int j = 0; j < 4; j++) {
            int col = wn * 32 + j * 8 + 2 * (lane & 3);
            float p00 = exp2f((sacc[j][0] - mn0) * LOG2E);
            float p01 = exp2f((sacc[j][1] - mn0) * LOG2E);
            float p10 = exp2f((sacc[j][2] - mn1) * LOG2E);
            float p11 = exp2f((sacc[j][3] - mn1) * LOG2E);
            rs0 += p00 + p01;
            rs1 += p10 + p11;
            *(uint2*)&Ps[lr0 * 68 + col] = make_uint2(f2tf(p00), f2tf(p01));
            *(uint2*)&Ps[lr1 * 68 + col] = make_uint2(f2tf(p10), f2tf(p11));
        }
#pragma unroll
        for (int off = 1; off <= 2; off <<= 1) {
            rs0 += __shfl_xor_sync(0xffffffffu, rs0, off);
            rs1 += __shfl_xor_sync(0xffffffffu, rs1, off);
        }
        if ((lane & 3) == 0) {
            sred[wn * 64 + lr0] = rs0;
            sred[wn * 64 + lr1] = rs1;
        }
        __syncthreads();
        float tot0 = sred[lr0] + sred[64 + lr0];
        float tot1 = sred[lr1] + sred[64 + lr1];

        float al0 = exp2f((m_i[0] - mn0) * LOG2E);   // 0 on first tile
        float al1 = exp2f((m_i[1] - mn1) * LOG2E);
        l_i[0] = l_i[0] * al0 + tot0;  m_i[0] = mn0;
        l_i[1] = l_i[1] * al1 + tot1;  m_i[1] = mn1;
#pragma unroll
        for (int nf = 0; nf < 8; nf++) {
            O[nf][0] *= al0; O[nf][1] *= al0;
            O[nf][2] *= al1; O[nf][3] *= al1;
        }

        // ---- O += P @ V (warp: rows wm*16..+16, cols wn*64..+64) ----
#pragma unroll
        for (int ks = 0; ks < 8; ks++) {
            const int kk = ks * 8 + (lane & 3);
            unsigned a[4];
            a[0] = Ps[lr0 * 68 + kk];
            a[1] = Ps[lr1 * 68 + kk];
            a[2] = Ps[lr0 * 68 + kk + 4];
            a[3] = Ps[lr1 * 68 + kk + 4];
#pragma unroll
            for (int nf = 0; nf < 8; nf++) {
                int n = wn * 64 + nf * 8 + (lane >> 2);
                unsigned b[2];
                b[0] = Vs[kk * 136 + n];
                b[1] = Vs[(kk + 4) * 136 + n];
                mma_tf32(O[nf], a, b);
            }
        }
    }

    // epilogue
    float inv0 = 1.0f / l_i[0];
    float inv1 = 1.0f / l_i[1];
    const int row0 = q0 + lr0, row1 = q0 + lr1;
#pragma unroll
    for (int nf = 0; nf < 8; nf++) {
        int col = h * HD + wn * 64 + nf * 8 + 2 * (lane & 3);
        *(float2*)&g_y[(size_t)row0 * DIM_ + col] = make_float2(O[nf][0] * inv0, O[nf][1] * inv0);
        *(float2*)&g_y[(size_t)row1 * DIM_ + col] = make_float2(O[nf][2] * inv1, O[nf][3] * inv1);
    }
}

// -------------------- launch ---------------------------------------------------------
extern "C" void kernel_launch(void* const* d_in, const int* in_sizes, int n_in,
                              void* d_out, int out_size)
{
    const float* x        = (const float*)d_in[0];
    const float* ve       = (const float*)d_in[1];
    const float* qkv_w    = (const float*)d_in[2];
    const float* lambdas  = (const float*)d_in[3];
    const float* c_proj_w = (const float*)d_in[4];
    float* out = (float*)d_out;

    float *p_qkv, *p_y;
    cudaGetSymbolAddress((void**)&p_qkv, g_qkv);
    cudaGetSymbolAddress((void**)&p_y,   g_y);

    // 1) QKV projection: g_qkv[2048,3072] = x[2048,1024] @ qkv_w^T
    gemm_nt_tc<<<dim3(3 * DIM_ / 128, T_SEQ / 128), 256>>>(x, qkv_w, p_qkv, T_SEQ, 3 * DIM_, DIM_);

    // 2) rmsnorm + rotary + v mix (outputs tf32-rounded)
    transform_kernel<<<dim3(T_SEQ, NH), 128>>>(ve, lambdas);

    // 3) causal flash attention (tensor core)
    cudaFuncSetAttribute(attn_tc, cudaFuncAttributeMaxDynamicSharedMemorySize,
                         ATT_SMEM_WORDS * (int)sizeof(unsigned));
    attn_tc<<<dim3((T_SEQ / 64) * NH), 256, ATT_SMEM_WORDS * sizeof(unsigned)>>>();

    // 4) output projection: out[2048,1024] = g_y @ c_proj_w^T
    gemm_nt_tc<<<dim3(DIM_ / 128, T_SEQ / 128), 256>>>(p_y, c_proj_w, out, T_SEQ, DIM_, DIM_);
}